// round 1
// baseline (speedup 1.0000x reference)
#include <cuda_runtime.h>
#include <math.h>
#include <stdint.h>

#define N_NODES 50000
#define N_EDGES 600000
#define C 128
#define EC 16
#define BN_EPS 1e-5f
#define ALPHA 0.5f

// ---------------- device scratch (no allocations allowed) ----------------
__device__ float g_xh[N_NODES * C];          // BN output (x0), also layer-0 h-in
__device__ float g_h[N_NODES * C];           // h after layer 0
__device__ float g_mgh[N_NODES * 512];       // [m(128) | gh(384)] per node
__device__ float g_agg[N_NODES * C];         // scatter accumulator
__device__ float g_gi[N_NODES * 384];        // gi = (agg/deg)@w_ih^T + b_ih
__device__ int   g_src[N_EDGES];
__device__ int   g_dst[N_EDGES];
__device__ float g_degf[N_NODES];
__device__ float g_invdeg[N_NODES];
__device__ float g_sum[C];
__device__ float g_sq[C];
__device__ float g_scale[C];
__device__ float g_shift[C];
__device__ float g_B0[128 * 512];            // [convW0 | w_hh^T]
__device__ float g_B1[128 * 512];            // [convW1 | w_hh^T]
__device__ float g_B2[128 * 384];            // w_ih^T
__device__ float g_bias512[512];             // [0...0 | b_hh]
__device__ int   g_is64;

// ---------------- edge_index dtype detection ----------------
// int64 small values => all 64-bit reads in [0, 2^31). int32 pairs combine to
// huge values almost surely. Perfect discriminator on random node ids.
__global__ void detect_kernel(const long long* __restrict__ raw) {
    __shared__ int bad;
    if (threadIdx.x == 0) bad = 0;
    __syncthreads();
    long long v = raw[threadIdx.x];   // 64 threads
    if (v < 0 || v >= (1LL << 31)) atomicExch(&bad, 1);
    __syncthreads();
    if (threadIdx.x == 0) g_is64 = bad ? 0 : 1;
}

__global__ void normalize_edges(const void* __restrict__ raw) {
    int e = blockIdx.x * blockDim.x + threadIdx.x;
    if (e >= N_EDGES) return;
    if (g_is64) {
        const long long* p = (const long long*)raw;
        g_src[e] = (int)p[e];
        g_dst[e] = (int)p[N_EDGES + e];
    } else {
        const int* p = (const int*)raw;
        g_src[e] = p[e];
        g_dst[e] = p[N_EDGES + e];
    }
}

// ---------------- zero kernels ----------------
__global__ void zero_pre() {
    int i = blockIdx.x * blockDim.x + threadIdx.x;
    if (i < N_NODES) g_degf[i] = 0.f;
    if (i < C) { g_sum[i] = 0.f; g_sq[i] = 0.f; }
}

__global__ void zero_agg() {
    int i = blockIdx.x * blockDim.x + threadIdx.x;
    int total = N_NODES * C;
    for (; i < total; i += gridDim.x * blockDim.x) g_agg[i] = 0.f;
}

// ---------------- degree ----------------
__global__ void deg_kernel() {
    int e = blockIdx.x * blockDim.x + threadIdx.x;
    if (e < N_EDGES) atomicAdd(&g_degf[g_dst[e]], 1.0f);
}

__global__ void invdeg_kernel() {
    int i = blockIdx.x * blockDim.x + threadIdx.x;
    if (i < N_NODES) g_invdeg[i] = 1.0f / fmaxf(g_degf[i], 1.0f);
}

// ---------------- batchnorm ----------------
__global__ void bn_stats(const float* __restrict__ x) {
    int c = threadIdx.x;  // 128 threads
    float s = 0.f, q = 0.f;
    for (int r = blockIdx.x; r < N_NODES; r += gridDim.x) {
        float v = x[(size_t)r * C + c];
        s += v; q += v * v;
    }
    atomicAdd(&g_sum[c], s);
    atomicAdd(&g_sq[c], q);
}

__global__ void bn_coef(const float* __restrict__ gamma, const float* __restrict__ beta) {
    int c = threadIdx.x;
    float mean = g_sum[c] / (float)N_NODES;
    float var = g_sq[c] / (float)N_NODES - mean * mean;
    float sc = gamma[c] * rsqrtf(var + BN_EPS);
    g_scale[c] = sc;
    g_shift[c] = beta[c] - mean * sc;
}

__global__ void bn_apply(const float* __restrict__ x) {
    int idx = blockIdx.x * blockDim.x + threadIdx.x;
    if (idx >= N_NODES * C) return;
    int c = idx & (C - 1);
    g_xh[idx] = x[idx] * g_scale[c] + g_shift[c];
}

// ---------------- weight prep ----------------
// g_B0/g_B1: [128,512] = [convW_i(k,j) | w_hh(j,k)] ; g_B2: [128,384] = w_ih(j,k)
__global__ void prep_weights(const float* __restrict__ convW,
                             const float* __restrict__ w_ih,
                             const float* __restrict__ w_hh,
                             const float* __restrict__ b_hh) {
    int idx = blockIdx.x * blockDim.x + threadIdx.x;
    int total = 128 * 512;
    for (int t = idx; t < total; t += gridDim.x * blockDim.x) {
        int k = t >> 9;          // /512
        int j = t & 511;
        float v0, v1;
        if (j < 128) {
            v0 = convW[k * 128 + j];
            v1 = convW[128 * 128 + k * 128 + j];
        } else {
            float w = w_hh[(j - 128) * 128 + k];
            v0 = w; v1 = w;
        }
        g_B0[t] = v0;
        g_B1[t] = v1;
        if (t < 128 * 384) {
            int k2 = t / 384, j2 = t % 384;
            g_B2[t] = w_ih[j2 * 128 + k2];
        }
        if (t < 512) g_bias512[t] = (t < 128) ? 0.f : b_hh[t - 128];
    }
}

// ---------------- fp32 GEMM: C[M x nb] = (A * rowScale) [M x 128] @ B [128 x nb] + bias
// block tile 128x128, 256 threads, 8x8 micro-tile (4+4 split), BK=32
__global__ __launch_bounds__(256, 2)
void gemm_k(const float* __restrict__ A, const float* __restrict__ rowScale,
            const float* __restrict__ B, int nb,
            const float* __restrict__ bias,
            float* __restrict__ Cmat, int M) {
    __shared__ float As[32][128];   // [k][row]
    __shared__ float Bs[32][128];   // [k][col]
    int tid = threadIdx.x;
    int tx = tid & 15, ty = tid >> 4;
    int rowBase = blockIdx.y * 128;
    int colBase = blockIdx.x * 128;

    float acc[8][8];
#pragma unroll
    for (int i = 0; i < 8; i++)
#pragma unroll
        for (int j = 0; j < 8; j++) acc[i][j] = 0.f;

    for (int k0 = 0; k0 < 128; k0 += 32) {
        // A tile: 128 rows x 32 k, stored transposed As[k][row]
#pragma unroll
        for (int i = 0; i < 4; i++) {
            int idx = tid + i * 256;
            int r = idx & 127;
            int kq = idx >> 7;   // 0..7, float4 index along k
            int grow = rowBase + r;
            float4 v = make_float4(0.f, 0.f, 0.f, 0.f);
            if (grow < M) {
                v = *(const float4*)(A + (size_t)grow * 128 + k0 + kq * 4);
                if (rowScale) {
                    float s = rowScale[grow];
                    v.x *= s; v.y *= s; v.z *= s; v.w *= s;
                }
            }
            As[kq * 4 + 0][r] = v.x;
            As[kq * 4 + 1][r] = v.y;
            As[kq * 4 + 2][r] = v.z;
            As[kq * 4 + 3][r] = v.w;
        }
        // B tile: 32 k x 128 cols
#pragma unroll
        for (int i = 0; i < 4; i++) {
            int idx = tid + i * 256;
            int kk = idx >> 5;
            int cq = idx & 31;
            *(float4*)&Bs[kk][cq * 4] =
                *(const float4*)(B + (size_t)(k0 + kk) * nb + colBase + cq * 4);
        }
        __syncthreads();
#pragma unroll
        for (int k = 0; k < 32; k++) {
            float4 a0 = *(const float4*)&As[k][ty * 4];
            float4 a1 = *(const float4*)&As[k][64 + ty * 4];
            float4 b0 = *(const float4*)&Bs[k][tx * 4];
            float4 b1 = *(const float4*)&Bs[k][64 + tx * 4];
            float av[8] = {a0.x, a0.y, a0.z, a0.w, a1.x, a1.y, a1.z, a1.w};
            float bv[8] = {b0.x, b0.y, b0.z, b0.w, b1.x, b1.y, b1.z, b1.w};
#pragma unroll
            for (int i = 0; i < 8; i++)
#pragma unroll
                for (int j = 0; j < 8; j++) acc[i][j] += av[i] * bv[j];
        }
        __syncthreads();
    }
    // epilogue
#pragma unroll
    for (int i = 0; i < 8; i++) {
        int r = rowBase + ((i < 4) ? (ty * 4 + i) : (64 + ty * 4 + i - 4));
        if (r < M) {
#pragma unroll
            for (int jh = 0; jh < 2; jh++) {
                int c = colBase + jh * 64 + tx * 4;
                float4 o;
                o.x = acc[i][jh * 4 + 0];
                o.y = acc[i][jh * 4 + 1];
                o.z = acc[i][jh * 4 + 2];
                o.w = acc[i][jh * 4 + 3];
                if (bias) {
                    o.x += bias[c]; o.y += bias[c + 1];
                    o.z += bias[c + 2]; o.w += bias[c + 3];
                }
                *(float4*)(Cmat + (size_t)r * nb + c) = o;
            }
        }
    }
}

// ---------------- edge kernel: one warp per edge ----------------
// ea = edge_attr[e] @ edge_W (computed on the fly); msg = relu(m[src]+ea);
// atomicAdd into agg[dst]. m lives in g_mgh cols [0,128), row stride 512.
__global__ void edge_kernel(const float* __restrict__ eattr,
                            const float* __restrict__ eW) {
    __shared__ float4 Ws[16 * 32];   // edge_W as float4: [k][lane]
    for (int i = threadIdx.x; i < 512; i += blockDim.x)
        Ws[i] = ((const float4*)eW)[i];
    __syncthreads();

    int warp = (blockIdx.x * blockDim.x + threadIdx.x) >> 5;
    int lane = threadIdx.x & 31;
    if (warp >= N_EDGES) return;

    int s = g_src[warp];
    int d = g_dst[warp];
    float a = (lane < EC) ? eattr[(size_t)warp * EC + lane] : 0.f;

    float4 ea = make_float4(0.f, 0.f, 0.f, 0.f);
#pragma unroll
    for (int k = 0; k < EC; k++) {
        float ak = __shfl_sync(0xffffffffu, a, k);
        float4 w = Ws[k * 32 + lane];
        ea.x += ak * w.x; ea.y += ak * w.y;
        ea.z += ak * w.z; ea.w += ak * w.w;
    }
    float4 m = *(const float4*)&g_mgh[(size_t)s * 512 + lane * 4];
    float vx = fmaxf(m.x + ea.x, 0.f);
    float vy = fmaxf(m.y + ea.y, 0.f);
    float vz = fmaxf(m.z + ea.z, 0.f);
    float vw = fmaxf(m.w + ea.w, 0.f);
    float* ap = &g_agg[(size_t)d * C + lane * 4];
    atomicAdd(ap + 0, vx);
    atomicAdd(ap + 1, vy);
    atomicAdd(ap + 2, vz);
    atomicAdd(ap + 3, vw);
}

// ---------------- GRU gates (+ optional final residual) ----------------
__global__ void gru_gates(const float* __restrict__ hin,
                          float* __restrict__ hout, int last) {
    int idx = blockIdx.x * blockDim.x + threadIdx.x;
    if (idx >= N_NODES * C) return;
    int n = idx >> 7;
    int c = idx & (C - 1);
    size_t gib = (size_t)n * 384;
    size_t mb = (size_t)n * 512;
    float ir = g_gi[gib + c];
    float iz = g_gi[gib + 128 + c];
    float in_ = g_gi[gib + 256 + c];
    float hr = g_mgh[mb + 128 + c];
    float hz = g_mgh[mb + 256 + c];
    float hn = g_mgh[mb + 384 + c];
    float r = 1.f / (1.f + expf(-(ir + hr)));
    float z = 1.f / (1.f + expf(-(iz + hz)));
    float nn = tanhf(in_ + r * hn);
    float h = hin[idx];
    float hnew = (1.f - z) * nn + z * h;
    if (last)
        hout[idx] = (1.f - ALPHA) * fmaxf(hnew, 0.f) + ALPHA * g_xh[idx];
    else
        hout[idx] = hnew;
}

// ---------------- host ----------------
extern "C" void kernel_launch(void* const* d_in, const int* in_sizes, int n_in,
                              void* d_out, int out_size) {
    const float* x     = (const float*)d_in[0];
    const void*  eidx  = d_in[1];
    const float* eattr = (const float*)d_in[2];
    const float* gamma = (const float*)d_in[3];
    const float* beta  = (const float*)d_in[4];
    const float* edgeW = (const float*)d_in[5];
    const float* convW = (const float*)d_in[6];
    const float* w_ih  = (const float*)d_in[7];
    const float* w_hh  = (const float*)d_in[8];
    const float* b_ih  = (const float*)d_in[9];
    const float* b_hh  = (const float*)d_in[10];
    float* out = (float*)d_out;
    (void)in_sizes; (void)n_in; (void)out_size;

    // resolve device-global scratch addresses (host API, capture-safe)
    float *xh, *h, *mgh, *agg, *gi, *invdeg, *B0, *B1, *B2, *bias512;
    void* p;
    cudaGetSymbolAddress(&p, g_xh);      xh = (float*)p;
    cudaGetSymbolAddress(&p, g_h);       h = (float*)p;
    cudaGetSymbolAddress(&p, g_mgh);     mgh = (float*)p;
    cudaGetSymbolAddress(&p, g_agg);     agg = (float*)p;
    cudaGetSymbolAddress(&p, g_gi);      gi = (float*)p;
    cudaGetSymbolAddress(&p, g_invdeg);  invdeg = (float*)p;
    cudaGetSymbolAddress(&p, g_B0);      B0 = (float*)p;
    cudaGetSymbolAddress(&p, g_B1);      B1 = (float*)p;
    cudaGetSymbolAddress(&p, g_B2);      B2 = (float*)p;
    cudaGetSymbolAddress(&p, g_bias512); bias512 = (float*)p;

    const int NC = N_NODES * C;

    detect_kernel<<<1, 64>>>((const long long*)eidx);
    normalize_edges<<<(N_EDGES + 255) / 256, 256>>>(eidx);
    zero_pre<<<(N_NODES + 255) / 256, 256>>>();
    bn_stats<<<512, 128>>>(x);
    deg_kernel<<<(N_EDGES + 255) / 256, 256>>>();
    invdeg_kernel<<<(N_NODES + 255) / 256, 256>>>();
    bn_coef<<<1, 128>>>(gamma, beta);
    bn_apply<<<(NC + 255) / 256, 256>>>(x);
    prep_weights<<<256, 256>>>(convW, w_ih, w_hh, b_hh);

    const int mtiles = (N_NODES + 127) / 128;   // 391

    for (int layer = 0; layer < 2; layer++) {
        const float* hin = (layer == 0) ? xh : h;
        float* Bcat = (layer == 0) ? B0 : B1;
        float* hout = (layer == 1) ? out : h;

        // mgh = hin @ [convW_i | w_hh^T] + [0 | b_hh]
        gemm_k<<<dim3(4, mtiles), 256>>>(hin, nullptr, Bcat, 512, bias512,
                                         mgh, N_NODES);
        zero_agg<<<6250, 1024>>>();
        edge_kernel<<<(N_EDGES + 7) / 8, 256>>>(eattr, edgeW);
        // gi = (agg * invdeg) @ w_ih^T + b_ih
        gemm_k<<<dim3(3, mtiles), 256>>>(agg, invdeg, B2, 384, b_ih,
                                         gi, N_NODES);
        gru_gates<<<(NC + 255) / 256, 256>>>(hin, hout, layer == 1 ? 1 : 0);
    }
}

// round 3
// speedup vs baseline: 1.3656x; 1.3656x over previous
#include <cuda_runtime.h>
#include <math.h>
#include <stdint.h>

#define N_NODES 50000
#define N_EDGES 600000
#define C 128
#define EC 16
#define BN_EPS 1e-5f
#define ALPHA 0.5f

// ---------------- device scratch (no allocations allowed) ----------------
__device__ float g_xh[N_NODES * C];          // BN output (x0), layer-0 h-in
__device__ float g_h[N_NODES * C];           // h after layer 0
__device__ float g_mgh[N_NODES * 512];       // [m(128) | gh(384)] per node
__device__ float g_agg[N_NODES * C];         // scatter accumulator
__device__ float g_gi[N_NODES * 384];        // gi = (agg/deg)@w_ih^T + b_ih
__device__ int   g_src[N_EDGES];
__device__ int   g_dst[N_EDGES];
__device__ float g_degf[N_NODES];
__device__ float g_invdeg[N_NODES];
__device__ float g_sum[C];
__device__ float g_sq[C];
__device__ float g_scale[C];
__device__ float g_shift[C];
__device__ float g_B0[512 * 128];            // transposed: row n, col k  [convW0 | w_hh]
__device__ float g_B1[512 * 128];            // transposed: row n, col k  [convW1 | w_hh]
__device__ float g_bias512[512];             // [0...0 | b_hh]
__device__ int   g_is64;

// ---------------- edge_index dtype detection ----------------
__global__ void detect_kernel(const long long* __restrict__ raw) {
    __shared__ int bad;
    if (threadIdx.x == 0) bad = 0;
    __syncthreads();
    long long v = raw[threadIdx.x];   // 64 threads
    if (v < 0 || v >= (1LL << 31)) atomicExch(&bad, 1);
    __syncthreads();
    if (threadIdx.x == 0) g_is64 = bad ? 0 : 1;
}

__global__ void normalize_edges(const void* __restrict__ raw) {
    int e = blockIdx.x * blockDim.x + threadIdx.x;
    if (e >= N_EDGES) return;
    if (g_is64) {
        const long long* p = (const long long*)raw;
        g_src[e] = (int)p[e];
        g_dst[e] = (int)p[N_EDGES + e];
    } else {
        const int* p = (const int*)raw;
        g_src[e] = p[e];
        g_dst[e] = p[N_EDGES + e];
    }
}

// ---------------- zero kernels ----------------
__global__ void zero_pre() {
    int i = blockIdx.x * blockDim.x + threadIdx.x;
    if (i < N_NODES) g_degf[i] = 0.f;
    if (i < C) { g_sum[i] = 0.f; g_sq[i] = 0.f; }
}

__global__ void zero_agg() {
    int i = blockIdx.x * blockDim.x + threadIdx.x;
    int total = N_NODES * C;
    for (; i < total; i += gridDim.x * blockDim.x) g_agg[i] = 0.f;
}

// ---------------- degree ----------------
__global__ void deg_kernel() {
    int e = blockIdx.x * blockDim.x + threadIdx.x;
    if (e < N_EDGES) atomicAdd(&g_degf[g_dst[e]], 1.0f);
}

__global__ void invdeg_kernel() {
    int i = blockIdx.x * blockDim.x + threadIdx.x;
    if (i < N_NODES) g_invdeg[i] = 1.0f / fmaxf(g_degf[i], 1.0f);
}

// ---------------- batchnorm ----------------
__global__ void bn_stats(const float* __restrict__ x) {
    int c = threadIdx.x;  // 128 threads
    float s = 0.f, q = 0.f;
    for (int r = blockIdx.x; r < N_NODES; r += gridDim.x) {
        float v = x[(size_t)r * C + c];
        s += v; q += v * v;
    }
    atomicAdd(&g_sum[c], s);
    atomicAdd(&g_sq[c], q);
}

__global__ void bn_coef(const float* __restrict__ gamma, const float* __restrict__ beta) {
    int c = threadIdx.x;
    float mean = g_sum[c] / (float)N_NODES;
    float var = g_sq[c] / (float)N_NODES - mean * mean;
    float sc = gamma[c] * rsqrtf(var + BN_EPS);
    g_scale[c] = sc;
    g_shift[c] = beta[c] - mean * sc;
}

__global__ void bn_apply(const float* __restrict__ x) {
    int idx = blockIdx.x * blockDim.x + threadIdx.x;
    if (idx >= N_NODES * C) return;
    int c = idx & (C - 1);
    g_xh[idx] = x[idx] * g_scale[c] + g_shift[c];
}

// ---------------- weight prep ----------------
// Transposed B (N-major, K contiguous): g_B0/g_B1[n][k]; n<128: convW_i[k][n],
// n>=128: w_hh[n-128][k].  GEMM2's B is w_ih itself ([384][128] row-major).
__global__ void prep_weights(const float* __restrict__ convW,
                             const float* __restrict__ w_hh,
                             const float* __restrict__ b_hh) {
    int idx = blockIdx.x * blockDim.x + threadIdx.x;
    int total = 512 * 128;
    for (int t = idx; t < total; t += gridDim.x * blockDim.x) {
        int n = t >> 7;
        int k = t & 127;
        float v0, v1;
        if (n < 128) {
            v0 = convW[k * 128 + n];
            v1 = convW[128 * 128 + k * 128 + n];
        } else {
            float w = w_hh[(n - 128) * 128 + k];
            v0 = w; v1 = w;
        }
        g_B0[t] = v0;
        g_B1[t] = v1;
        if (t < 512) g_bias512[t] = (t < 128) ? 0.f : b_hh[t - 128];
    }
}

// ---------------- tf32 tensor-core GEMM (mma.sync, sm_80+ path) ----------------
// C[M x nb] = (A * rowScale)[M x 128] @ Bt^T + bias; Bt stored [nb][128] K-major.
// CTA = 128x128 output tile, 256 threads = 8 warps (2 M x 4 N), warp = 64x32.
// SMEM: As[128][132], Bs[128][132] (pad 132 -> fragment loads conflict-free).
#define SPAD 132
#define TILE_SMEM (2 * 128 * SPAD * 4)

__device__ __forceinline__ uint32_t f2tf(float f) {
    uint32_t r;
    asm("cvt.rna.tf32.f32 %0, %1;" : "=r"(r) : "f"(f));
    return r;
}

__device__ __forceinline__ void mma_tf32(float* d, const uint32_t* a,
                                         const uint32_t* b) {
    asm volatile(
        "mma.sync.aligned.m16n8k8.row.col.f32.tf32.tf32.f32 "
        "{%0,%1,%2,%3}, {%4,%5,%6,%7}, {%8,%9}, {%0,%1,%2,%3};\n"
        : "+f"(d[0]), "+f"(d[1]), "+f"(d[2]), "+f"(d[3])
        : "r"(a[0]), "r"(a[1]), "r"(a[2]), "r"(a[3]),
          "r"(b[0]), "r"(b[1]));
}

__global__ __launch_bounds__(256, 1)
void gemm_tc(const float* __restrict__ A, const float* __restrict__ rowScale,
             const float* __restrict__ Bt, int nb,
             const float* __restrict__ bias,
             float* __restrict__ Cmat, int M) {
    extern __shared__ float smf[];
    float* As = smf;                 // [128][SPAD], row m, col k (tf32 bits)
    float* Bs = smf + 128 * SPAD;    // [128][SPAD], row n, col k (tf32 bits)

    int tid = threadIdx.x;
    int wid = tid >> 5;
    int lane = tid & 31;
    int rowBase = blockIdx.y * 128;
    int colBase = blockIdx.x * 128;

    // ---- load + convert A tile ----
#pragma unroll
    for (int i = 0; i < 16; i++) {
        int idx = tid + i * 256;     // float4 index
        int r = idx >> 5;
        int k4 = idx & 31;
        int grow = rowBase + r;
        float4 v = make_float4(0.f, 0.f, 0.f, 0.f);
        if (grow < M) {
            v = *(const float4*)(A + (size_t)grow * 128 + k4 * 4);
            if (rowScale) {
                float s = rowScale[grow];
                v.x *= s; v.y *= s; v.z *= s; v.w *= s;
            }
        }
        uint4 t = make_uint4(f2tf(v.x), f2tf(v.y), f2tf(v.z), f2tf(v.w));
        *(uint4*)&As[r * SPAD + k4 * 4] = t;
    }
    // ---- load + convert B tile ----
#pragma unroll
    for (int i = 0; i < 16; i++) {
        int idx = tid + i * 256;
        int n = idx >> 5;
        int k4 = idx & 31;
        float4 v = *(const float4*)(Bt + (size_t)(colBase + n) * 128 + k4 * 4);
        uint4 t = make_uint4(f2tf(v.x), f2tf(v.y), f2tf(v.z), f2tf(v.w));
        *(uint4*)&Bs[n * SPAD + k4 * 4] = t;
    }
    __syncthreads();

    // warp tiling: warpM = wid>>2 (0..1) -> 64 rows; warpN = wid&3 -> 32 cols
    int mBase = (wid >> 2) * 64;
    int nBase = (wid & 3) * 32;
    int qr = lane >> 2;              // 0..7
    int qc = lane & 3;               // 0..3

    float acc[4][4][4];
#pragma unroll
    for (int mi = 0; mi < 4; mi++)
#pragma unroll
        for (int ni = 0; ni < 4; ni++)
#pragma unroll
            for (int q = 0; q < 4; q++) acc[mi][ni][q] = 0.f;

    const uint32_t* Au = (const uint32_t*)As;
    const uint32_t* Bu = (const uint32_t*)Bs;

#pragma unroll
    for (int k0 = 0; k0 < 128; k0 += 8) {
        uint32_t afr[4][4];
#pragma unroll
        for (int mi = 0; mi < 4; mi++) {
            int r0 = mBase + mi * 16 + qr;
            afr[mi][0] = Au[r0 * SPAD + k0 + qc];
            afr[mi][1] = Au[(r0 + 8) * SPAD + k0 + qc];
            afr[mi][2] = Au[r0 * SPAD + k0 + qc + 4];
            afr[mi][3] = Au[(r0 + 8) * SPAD + k0 + qc + 4];
        }
        uint32_t bfr[4][2];
#pragma unroll
        for (int ni = 0; ni < 4; ni++) {
            int n0 = nBase + ni * 8 + qr;
            bfr[ni][0] = Bu[n0 * SPAD + k0 + qc];
            bfr[ni][1] = Bu[n0 * SPAD + k0 + qc + 4];
        }
#pragma unroll
        for (int mi = 0; mi < 4; mi++)
#pragma unroll
            for (int ni = 0; ni < 4; ni++)
                mma_tf32(acc[mi][ni], afr[mi], bfr[ni]);
    }

    // ---- epilogue ----
#pragma unroll
    for (int mi = 0; mi < 4; mi++) {
        int r0 = rowBase + mBase + mi * 16 + qr;
#pragma unroll
        for (int ni = 0; ni < 4; ni++) {
            int cc = colBase + nBase + ni * 8 + qc * 2;
            float2 bv = *(const float2*)(bias + cc);
            if (r0 < M) {
                float2 o0 = make_float2(acc[mi][ni][0] + bv.x,
                                        acc[mi][ni][1] + bv.y);
                *(float2*)(Cmat + (size_t)r0 * nb + cc) = o0;
            }
            if (r0 + 8 < M) {
                float2 o1 = make_float2(acc[mi][ni][2] + bv.x,
                                        acc[mi][ni][3] + bv.y);
                *(float2*)(Cmat + (size_t)(r0 + 8) * nb + cc) = o1;
            }
        }
    }
}

// ---------------- edge kernel: one warp per edge ----------------
__global__ void edge_kernel(const float* __restrict__ eattr,
                            const float* __restrict__ eW) {
    __shared__ float4 Ws[16 * 32];   // edge_W as float4: [k][lane]
    for (int i = threadIdx.x; i < 512; i += blockDim.x)
        Ws[i] = ((const float4*)eW)[i];
    __syncthreads();

    int warp = (blockIdx.x * blockDim.x + threadIdx.x) >> 5;
    int lane = threadIdx.x & 31;
    if (warp >= N_EDGES) return;

    int s = g_src[warp];
    int d = g_dst[warp];
    float a = (lane < EC) ? eattr[(size_t)warp * EC + lane] : 0.f;

    float4 ea = make_float4(0.f, 0.f, 0.f, 0.f);
#pragma unroll
    for (int k = 0; k < EC; k++) {
        float ak = __shfl_sync(0xffffffffu, a, k);
        float4 w = Ws[k * 32 + lane];
        ea.x += ak * w.x; ea.y += ak * w.y;
        ea.z += ak * w.z; ea.w += ak * w.w;
    }
    float4 m = *(const float4*)&g_mgh[(size_t)s * 512 + lane * 4];
    float vx = fmaxf(m.x + ea.x, 0.f);
    float vy = fmaxf(m.y + ea.y, 0.f);
    float vz = fmaxf(m.z + ea.z, 0.f);
    float vw = fmaxf(m.w + ea.w, 0.f);
    float* ap = &g_agg[(size_t)d * C + lane * 4];
    atomicAdd(ap + 0, vx);
    atomicAdd(ap + 1, vy);
    atomicAdd(ap + 2, vz);
    atomicAdd(ap + 3, vw);
}

// ---------------- GRU gates (+ optional final residual) ----------------
__global__ void gru_gates(const float* __restrict__ hin,
                          float* __restrict__ hout, int last) {
    int idx = blockIdx.x * blockDim.x + threadIdx.x;
    if (idx >= N_NODES * C) return;
    int n = idx >> 7;
    int c = idx & (C - 1);
    size_t gib = (size_t)n * 384;
    size_t mb = (size_t)n * 512;
    float ir = g_gi[gib + c];
    float iz = g_gi[gib + 128 + c];
    float in_ = g_gi[gib + 256 + c];
    float hr = g_mgh[mb + 128 + c];
    float hz = g_mgh[mb + 256 + c];
    float hn = g_mgh[mb + 384 + c];
    float r = 1.f / (1.f + expf(-(ir + hr)));
    float z = 1.f / (1.f + expf(-(iz + hz)));
    float nn = tanhf(in_ + r * hn);
    float h = hin[idx];
    float hnew = (1.f - z) * nn + z * h;
    if (last)
        hout[idx] = (1.f - ALPHA) * fmaxf(hnew, 0.f) + ALPHA * g_xh[idx];
    else
        hout[idx] = hnew;
}

// ---------------- host ----------------
extern "C" void kernel_launch(void* const* d_in, const int* in_sizes, int n_in,
                              void* d_out, int out_size) {
    const float* x     = (const float*)d_in[0];
    const void*  eidx  = d_in[1];
    const float* eattr = (const float*)d_in[2];
    const float* gamma = (const float*)d_in[3];
    const float* beta  = (const float*)d_in[4];
    const float* edgeW = (const float*)d_in[5];
    const float* convW = (const float*)d_in[6];
    const float* w_ih  = (const float*)d_in[7];
    const float* w_hh  = (const float*)d_in[8];
    const float* b_ih  = (const float*)d_in[9];
    const float* b_hh  = (const float*)d_in[10];
    float* out = (float*)d_out;
    (void)in_sizes; (void)n_in; (void)out_size;

    float *xh, *h, *mgh, *agg, *gi, *invdeg, *B0, *B1, *bias512;
    void* p;
    cudaGetSymbolAddress(&p, g_xh);      xh = (float*)p;
    cudaGetSymbolAddress(&p, g_h);       h = (float*)p;
    cudaGetSymbolAddress(&p, g_mgh);     mgh = (float*)p;
    cudaGetSymbolAddress(&p, g_agg);     agg = (float*)p;
    cudaGetSymbolAddress(&p, g_gi);      gi = (float*)p;
    cudaGetSymbolAddress(&p, g_invdeg);  invdeg = (float*)p;
    cudaGetSymbolAddress(&p, g_B0);      B0 = (float*)p;
    cudaGetSymbolAddress(&p, g_B1);      B1 = (float*)p;
    cudaGetSymbolAddress(&p, g_bias512); bias512 = (float*)p;

    static int attr_done = 0;
    if (!attr_done) {
        cudaFuncSetAttribute(gemm_tc, cudaFuncAttributeMaxDynamicSharedMemorySize,
                             TILE_SMEM);
        attr_done = 1;
    }

    const int NC = N_NODES * C;

    detect_kernel<<<1, 64>>>((const long long*)eidx);
    normalize_edges<<<(N_EDGES + 255) / 256, 256>>>(eidx);
    zero_pre<<<(N_NODES + 255) / 256, 256>>>();
    bn_stats<<<2048, 128>>>(x);
    deg_kernel<<<(N_EDGES + 255) / 256, 256>>>();
    invdeg_kernel<<<(N_NODES + 255) / 256, 256>>>();
    bn_coef<<<1, 128>>>(gamma, beta);
    bn_apply<<<(NC + 255) / 256, 256>>>(x);
    prep_weights<<<256, 256>>>(convW, w_hh, b_hh);

    const int mtiles = (N_NODES + 127) / 128;   // 391

    for (int layer = 0; layer < 2; layer++) {
        const float* hin = (layer == 0) ? xh : h;
        float* Bcat = (layer == 0) ? B0 : B1;
        float* hout = (layer == 1) ? out : h;

        // mgh = hin @ [convW_i | w_hh^T] + [0 | b_hh]
        gemm_tc<<<dim3(4, mtiles), 256, TILE_SMEM>>>(hin, nullptr, Bcat, 512,
                                                     bias512, mgh, N_NODES);
        zero_agg<<<6250, 1024>>>();
        edge_kernel<<<(N_EDGES + 7) / 8, 256>>>(eattr, edgeW);
        // gi = (agg * invdeg) @ w_ih^T + b_ih   (B = w_ih, already [384][128])
        gemm_tc<<<dim3(3, mtiles), 256, TILE_SMEM>>>(agg, invdeg, w_ih, 384,
                                                     b_ih, gi, N_NODES);
        gru_gates<<<(NC + 255) / 256, 256>>>(hin, hout, layer == 1 ? 1 : 0);
    }
}

// round 4
// speedup vs baseline: 1.8623x; 1.3637x over previous
#include <cuda_runtime.h>
#include <cuda_bf16.h>
#include <math.h>
#include <stdint.h>

#define N_NODES 50000
#define N_EDGES 600000
#define C 128
#define EC 16
#define BN_EPS 1e-5f
#define ALPHA 0.5f

typedef __nv_bfloat16 bf16;
typedef __nv_bfloat162 bf162;

// ---------------- device scratch (no allocations allowed) ----------------
__device__ float g_xh[N_NODES * C];          // BN output (x0) fp32
__device__ bf16  g_xhh[N_NODES * C];         // BN output bf16 (GEMM A)
__device__ float g_h[N_NODES * C];           // h after layer 0 (fp32)
__device__ bf16  g_hh[N_NODES * C];          // h bf16 (GEMM A, layer 1)
__device__ float g_mgh[N_NODES * 512];       // [m(128) | gh(384)] fp32
__device__ bf16  g_mh[N_NODES * C];          // bf16 copy of m (gather source)
__device__ bf16  g_aggh[N_NODES * C];        // (agg/deg) bf16 (GEMM2 A)
__device__ float g_gi[N_NODES * 384];        // gi fp32
__device__ int   g_src[N_EDGES];
__device__ int   g_dst[N_EDGES];
__device__ int   g_csr_src[N_EDGES];
__device__ int   g_csr_eid[N_EDGES];
__device__ int   g_degi[N_NODES];
__device__ int   g_ptr[N_NODES + 1];
__device__ int   g_cur[N_NODES];
__device__ int   g_bsum[256];
__device__ int   g_boff[256];
__device__ float g_invdeg[N_NODES];
__device__ float g_sum[C];
__device__ float g_sq[C];
__device__ float g_scale[C];
__device__ float g_shift[C];
__device__ bf16  g_B0h[512 * 128];           // [convW0^T | w_hh] rows n, k contig
__device__ bf16  g_B1h[512 * 128];           // [convW1^T | w_hh]
__device__ bf16  g_B2h[384 * 128];           // w_ih (already [384][128] k-contig)
__device__ float g_bias512[512];             // [0...0 | b_hh]
__device__ int   g_is64;

// ---------------- small PTX helpers ----------------
__device__ __forceinline__ uint32_t smem_u32(const void* p) {
    uint32_t a;
    asm("{ .reg .u64 t; cvta.to.shared.u64 t, %1; cvt.u32.u64 %0, t; }"
        : "=r"(a) : "l"(p));
    return a;
}
__device__ __forceinline__ void ldmx4(uint32_t* r, uint32_t addr) {
    asm volatile("ldmatrix.sync.aligned.m8n8.x4.shared.b16 {%0,%1,%2,%3}, [%4];"
        : "=r"(r[0]), "=r"(r[1]), "=r"(r[2]), "=r"(r[3]) : "r"(addr));
}
__device__ __forceinline__ void mma_bf16(float* d, const uint32_t* a,
                                         const uint32_t* b) {
    asm volatile(
        "mma.sync.aligned.m16n8k16.row.col.f32.bf16.bf16.f32 "
        "{%0,%1,%2,%3}, {%4,%5,%6,%7}, {%8,%9}, {%0,%1,%2,%3};"
        : "+f"(d[0]), "+f"(d[1]), "+f"(d[2]), "+f"(d[3])
        : "r"(a[0]), "r"(a[1]), "r"(a[2]), "r"(a[3]), "r"(b[0]), "r"(b[1]));
}

// ---------------- edge_index dtype detection ----------------
__global__ void detect_kernel(const long long* __restrict__ raw) {
    __shared__ int bad;
    if (threadIdx.x == 0) bad = 0;
    __syncthreads();
    long long v = raw[threadIdx.x];   // 64 threads
    if (v < 0 || v >= (1LL << 31)) atomicExch(&bad, 1);
    __syncthreads();
    if (threadIdx.x == 0) g_is64 = bad ? 0 : 1;
}

__global__ void normalize_edges(const void* __restrict__ raw) {
    int e = blockIdx.x * blockDim.x + threadIdx.x;
    if (e >= N_EDGES) return;
    if (g_is64) {
        const long long* p = (const long long*)raw;
        g_src[e] = (int)p[e];
        g_dst[e] = (int)p[N_EDGES + e];
    } else {
        const int* p = (const int*)raw;
        g_src[e] = p[e];
        g_dst[e] = p[N_EDGES + e];
    }
}

// ---------------- zero / degree / CSR build ----------------
__global__ void zero_pre() {
    int i = blockIdx.x * blockDim.x + threadIdx.x;
    if (i < N_NODES) g_degi[i] = 0;
    if (i < C) { g_sum[i] = 0.f; g_sq[i] = 0.f; }
}

__global__ void deg_kernel() {
    int e = blockIdx.x * blockDim.x + threadIdx.x;
    if (e < N_EDGES) atomicAdd(&g_degi[g_dst[e]], 1);
}

__global__ void invdeg_kernel() {
    int i = blockIdx.x * blockDim.x + threadIdx.x;
    if (i < N_NODES) g_invdeg[i] = 1.0f / fmaxf((float)g_degi[i], 1.0f);
}

#define SCAN_BLOCKS 196
__global__ void scan_part() {           // 196 x 256
    __shared__ int sh[256];
    int i = blockIdx.x * 256 + threadIdx.x;
    sh[threadIdx.x] = (i < N_NODES) ? g_degi[i] : 0;
    __syncthreads();
    for (int s = 128; s > 0; s >>= 1) {
        if (threadIdx.x < s) sh[threadIdx.x] += sh[threadIdx.x + s];
        __syncthreads();
    }
    if (threadIdx.x == 0) g_bsum[blockIdx.x] = sh[0];
}

__global__ void scan_top() {            // 1 x 256
    __shared__ int sh[256];
    int t = threadIdx.x;
    int own = (t < SCAN_BLOCKS) ? g_bsum[t] : 0;
    sh[t] = own;
    __syncthreads();
    for (int s = 1; s < 256; s <<= 1) {
        int v = (t >= s) ? sh[t - s] : 0;
        __syncthreads();
        sh[t] += v;
        __syncthreads();
    }
    if (t < SCAN_BLOCKS) g_boff[t] = sh[t] - own;   // exclusive
}

__global__ void scan_block() {          // 196 x 256
    __shared__ int sh[256];
    int t = threadIdx.x;
    int i = blockIdx.x * 256 + t;
    int v = (i < N_NODES) ? g_degi[i] : 0;
    sh[t] = v;
    __syncthreads();
    for (int s = 1; s < 256; s <<= 1) {
        int u = (t >= s) ? sh[t - s] : 0;
        __syncthreads();
        sh[t] += u;
        __syncthreads();
    }
    int excl = sh[t] - v + g_boff[blockIdx.x];
    if (i < N_NODES) { g_ptr[i] = excl; g_cur[i] = excl; }
    if (i == N_NODES - 1) g_ptr[N_NODES] = excl + v;
}

__global__ void scatter_k() {
    int e = blockIdx.x * blockDim.x + threadIdx.x;
    if (e >= N_EDGES) return;
    int pos = atomicAdd(&g_cur[g_dst[e]], 1);
    g_csr_src[pos] = g_src[e];
    g_csr_eid[pos] = e;
}

// ---------------- batchnorm ----------------
__global__ void bn_stats(const float* __restrict__ x) {
    int c = threadIdx.x;  // 128 threads
    float s = 0.f, q = 0.f;
    for (int r = blockIdx.x; r < N_NODES; r += gridDim.x) {
        float v = x[(size_t)r * C + c];
        s += v; q += v * v;
    }
    atomicAdd(&g_sum[c], s);
    atomicAdd(&g_sq[c], q);
}

__global__ void bn_coef(const float* __restrict__ gamma, const float* __restrict__ beta) {
    int c = threadIdx.x;
    float mean = g_sum[c] / (float)N_NODES;
    float var = g_sq[c] / (float)N_NODES - mean * mean;
    float sc = gamma[c] * rsqrtf(var + BN_EPS);
    g_scale[c] = sc;
    g_shift[c] = beta[c] - mean * sc;
}

__global__ void bn_apply(const float* __restrict__ x) {
    int idx = blockIdx.x * blockDim.x + threadIdx.x;
    if (idx >= N_NODES * C) return;
    int c = idx & (C - 1);
    float v = x[idx] * g_scale[c] + g_shift[c];
    g_xh[idx] = v;
    g_xhh[idx] = __float2bfloat16(v);
}

// ---------------- weight prep (bf16) ----------------
__global__ void prep_weights(const float* __restrict__ convW,
                             const float* __restrict__ w_ih,
                             const float* __restrict__ w_hh,
                             const float* __restrict__ b_hh) {
    int idx = blockIdx.x * blockDim.x + threadIdx.x;
    int total = 512 * 128;
    for (int t = idx; t < total; t += gridDim.x * blockDim.x) {
        int n = t >> 7;
        int k = t & 127;
        float v0, v1;
        if (n < 128) {
            v0 = convW[k * 128 + n];
            v1 = convW[128 * 128 + k * 128 + n];
        } else {
            float w = w_hh[(n - 128) * 128 + k];
            v0 = w; v1 = w;
        }
        g_B0h[t] = __float2bfloat16(v0);
        g_B1h[t] = __float2bfloat16(v1);
        if (t < 384 * 128) g_B2h[t] = __float2bfloat16(w_ih[t]);
        if (t < 512) g_bias512[t] = (t < 128) ? 0.f : b_hh[t - 128];
    }
}

// ---------------- bf16 tensor-core GEMM ----------------
// C[M x nb] = A[M x 128] @ Bt^T + bias; Bt [nb][128] k-contiguous, both bf16.
// CTA 128x128, 256 threads = 8 warps (2M x 4N), warp 64x32, ldmatrix + cp.async.
// If mcopy != null, cols [0,128) are also written as bf16 to mcopy[M][128].
#define SPADH 136                       // halfs per smem row (272B: LDSM conflict-free)
#define ASH_BYTES (128 * SPADH * 2)     // 34816
#define TILE_SMEM (2 * ASH_BYTES)       // 69632

__global__ __launch_bounds__(256, 2)
void gemm_bf16(const bf16* __restrict__ A, const bf16* __restrict__ Bt, int nb,
               const float* __restrict__ bias, float* __restrict__ Cmat,
               bf16* __restrict__ mcopy, int M) {
    extern __shared__ bf16 smh[];
    bf16* As = smh;                     // [128][SPADH]
    bf16* Bs = smh + 128 * SPADH;

    int tid = threadIdx.x, wid = tid >> 5, lane = tid & 31;
    int rowBase = blockIdx.y * 128, colBase = blockIdx.x * 128;
    uint32_t As_u = smem_u32(As), Bs_u = smem_u32(Bs);

    // ---- async tile loads (bf16, 16B chunks) ----
#pragma unroll
    for (int i = 0; i < 8; i++) {
        int c = tid + i * 256;
        int r = c >> 4, o = c & 15;
        int grow = rowBase + r;
        uint32_t sa = As_u + r * (SPADH * 2) + o * 16;
        int gr = (grow < M) ? grow : (M - 1);
        const void* ga = A + (size_t)gr * 128 + o * 8;
        uint32_t sz = (grow < M) ? 16u : 0u;
        asm volatile("cp.async.cg.shared.global [%0], [%1], 16, %2;"
                     :: "r"(sa), "l"(ga), "r"(sz));
    }
#pragma unroll
    for (int i = 0; i < 8; i++) {
        int c = tid + i * 256;
        int r = c >> 4, o = c & 15;
        uint32_t sa = Bs_u + r * (SPADH * 2) + o * 16;
        const void* ga = Bt + (size_t)(colBase + r) * 128 + o * 8;
        asm volatile("cp.async.cg.shared.global [%0], [%1], 16;"
                     :: "r"(sa), "l"(ga));
    }
    asm volatile("cp.async.commit_group;");
    asm volatile("cp.async.wait_group 0;" ::: "memory");
    __syncthreads();

    int mBase = (wid >> 2) * 64, nBase = (wid & 3) * 32;
    int mat = lane >> 3, rin = lane & 7;

    uint32_t aAddr[4];
#pragma unroll
    for (int mi = 0; mi < 4; mi++) {
        int row = mBase + mi * 16 + (mat & 1) * 8 + rin;
        int koff = (mat >> 1) * 8;
        aAddr[mi] = As_u + row * (SPADH * 2) + koff * 2;
    }
    uint32_t bAddr[2];
#pragma unroll
    for (int j = 0; j < 2; j++) {
        int row = nBase + j * 16 + (mat >> 1) * 8 + rin;
        int koff = (mat & 1) * 8;
        bAddr[j] = Bs_u + row * (SPADH * 2) + koff * 2;
    }

    float acc[4][4][4] = {};
#pragma unroll
    for (int ks = 0; ks < 8; ks++) {
        uint32_t afr[4][4], bfr[2][4];
#pragma unroll
        for (int mi = 0; mi < 4; mi++) ldmx4(afr[mi], aAddr[mi] + ks * 32);
#pragma unroll
        for (int j = 0; j < 2; j++) ldmx4(bfr[j], bAddr[j] + ks * 32);
#pragma unroll
        for (int mi = 0; mi < 4; mi++) {
            mma_bf16(acc[mi][0], afr[mi], &bfr[0][0]);
            mma_bf16(acc[mi][1], afr[mi], &bfr[0][2]);
            mma_bf16(acc[mi][2], afr[mi], &bfr[1][0]);
            mma_bf16(acc[mi][3], afr[mi], &bfr[1][2]);
        }
    }

    // ---- epilogue ----
    int qr = lane >> 2, qc = lane & 3;
#pragma unroll
    for (int mi = 0; mi < 4; mi++) {
        int r0 = rowBase + mBase + mi * 16 + qr;
#pragma unroll
        for (int ni = 0; ni < 4; ni++) {
            int cc = colBase + nBase + ni * 8 + qc * 2;
            float2 bv = *(const float2*)(bias + cc);
            float2 o0 = make_float2(acc[mi][ni][0] + bv.x, acc[mi][ni][1] + bv.y);
            float2 o1 = make_float2(acc[mi][ni][2] + bv.x, acc[mi][ni][3] + bv.y);
            if (r0 < M) {
                *(float2*)(Cmat + (size_t)r0 * nb + cc) = o0;
                if (mcopy && cc < 128)
                    *(bf162*)(mcopy + (size_t)r0 * 128 + cc) =
                        __float22bfloat162_rn(o0);
            }
            if (r0 + 8 < M) {
                *(float2*)(Cmat + (size_t)(r0 + 8) * nb + cc) = o1;
                if (mcopy && cc < 128)
                    *(bf162*)(mcopy + (size_t)(r0 + 8) * 128 + cc) =
                        __float22bfloat162_rn(o1);
            }
        }
    }
}

// ---------------- CSR aggregation: one warp per node ----------------
// agg[v] = invdeg[v] * sum_{e in CSR[v]} relu(m_bf16[src_e] + eattr[e]@edge_W)
__global__ void agg_csr(const float* __restrict__ eattr,
                        const float* __restrict__ eW) {
    __shared__ float4 Ws[16 * 32];    // edge_W fp32, [k][lane-of-4-cols]
    for (int i = threadIdx.x; i < 512; i += blockDim.x)
        Ws[i] = ((const float4*)eW)[i];
    __syncthreads();

    int warp = (blockIdx.x * blockDim.x + threadIdx.x) >> 5;
    int lane = threadIdx.x & 31;
    if (warp >= N_NODES) return;

    int beg = g_ptr[warp], end = g_ptr[warp + 1];
    float4 acc = make_float4(0.f, 0.f, 0.f, 0.f);

    for (int e = beg; e < end; e++) {
        int s = g_csr_src[e];
        int eid = g_csr_eid[e];
        float a = (lane < EC) ? eattr[(size_t)eid * EC + lane] : 0.f;
        float4 ea = make_float4(0.f, 0.f, 0.f, 0.f);
#pragma unroll
        for (int k = 0; k < EC; k++) {
            float ak = __shfl_sync(0xffffffffu, a, k);
            float4 w = Ws[k * 32 + lane];
            ea.x += ak * w.x; ea.y += ak * w.y;
            ea.z += ak * w.z; ea.w += ak * w.w;
        }
        uint2 mv = *(const uint2*)&g_mh[(size_t)s * C + lane * 4];
        float2 m01 = __bfloat1622float2(*(bf162*)&mv.x);
        float2 m23 = __bfloat1622float2(*(bf162*)&mv.y);
        acc.x += fmaxf(m01.x + ea.x, 0.f);
        acc.y += fmaxf(m01.y + ea.y, 0.f);
        acc.z += fmaxf(m23.x + ea.z, 0.f);
        acc.w += fmaxf(m23.y + ea.w, 0.f);
    }
    float sc = g_invdeg[warp];
    bf162 p0 = __float22bfloat162_rn(make_float2(acc.x * sc, acc.y * sc));
    bf162 p1 = __float22bfloat162_rn(make_float2(acc.z * sc, acc.w * sc));
    uint2 st;
    st.x = *(uint32_t*)&p0;
    st.y = *(uint32_t*)&p1;
    *(uint2*)&g_aggh[(size_t)warp * C + lane * 4] = st;
}

// ---------------- GRU gates (+ optional final residual) ----------------
__global__ void gru_gates(const float* __restrict__ hin,
                          float* __restrict__ hout, bf16* __restrict__ houth,
                          int last) {
    int idx = blockIdx.x * blockDim.x + threadIdx.x;
    if (idx >= N_NODES * C) return;
    int n = idx >> 7;
    int c = idx & (C - 1);
    size_t gib = (size_t)n * 384;
    size_t mb = (size_t)n * 512;
    float ir = g_gi[gib + c];
    float iz = g_gi[gib + 128 + c];
    float in_ = g_gi[gib + 256 + c];
    float hr = g_mgh[mb + 128 + c];
    float hz = g_mgh[mb + 256 + c];
    float hn = g_mgh[mb + 384 + c];
    float r = 1.f / (1.f + expf(-(ir + hr)));
    float z = 1.f / (1.f + expf(-(iz + hz)));
    float nn = tanhf(in_ + r * hn);
    float h = hin[idx];
    float hnew = (1.f - z) * nn + z * h;
    if (last) {
        hout[idx] = (1.f - ALPHA) * fmaxf(hnew, 0.f) + ALPHA * g_xh[idx];
    } else {
        hout[idx] = hnew;
        houth[idx] = __float2bfloat16(hnew);
    }
}

// ---------------- host ----------------
extern "C" void kernel_launch(void* const* d_in, const int* in_sizes, int n_in,
                              void* d_out, int out_size) {
    const float* x     = (const float*)d_in[0];
    const void*  eidx  = d_in[1];
    const float* eattr = (const float*)d_in[2];
    const float* gamma = (const float*)d_in[3];
    const float* beta  = (const float*)d_in[4];
    const float* edgeW = (const float*)d_in[5];
    const float* convW = (const float*)d_in[6];
    const float* w_ih  = (const float*)d_in[7];
    const float* w_hh  = (const float*)d_in[8];
    const float* b_ih  = (const float*)d_in[9];
    const float* b_hh  = (const float*)d_in[10];
    float* out = (float*)d_out;
    (void)in_sizes; (void)n_in; (void)out_size;

    float *xh, *h, *mgh, *gi, *bias512;
    bf16 *xhh, *hh, *mh, *aggh, *B0h, *B1h, *B2h;
    void* p;
    cudaGetSymbolAddress(&p, g_xh);      xh = (float*)p;
    cudaGetSymbolAddress(&p, g_xhh);     xhh = (bf16*)p;
    cudaGetSymbolAddress(&p, g_h);       h = (float*)p;
    cudaGetSymbolAddress(&p, g_hh);      hh = (bf16*)p;
    cudaGetSymbolAddress(&p, g_mgh);     mgh = (float*)p;
    cudaGetSymbolAddress(&p, g_mh);      mh = (bf16*)p;
    cudaGetSymbolAddress(&p, g_aggh);    aggh = (bf16*)p;
    cudaGetSymbolAddress(&p, g_gi);      gi = (float*)p;
    cudaGetSymbolAddress(&p, g_B0h);     B0h = (bf16*)p;
    cudaGetSymbolAddress(&p, g_B1h);     B1h = (bf16*)p;
    cudaGetSymbolAddress(&p, g_B2h);     B2h = (bf16*)p;
    cudaGetSymbolAddress(&p, g_bias512); bias512 = (float*)p;

    static int attr_done = 0;
    if (!attr_done) {
        cudaFuncSetAttribute(gemm_bf16, cudaFuncAttributeMaxDynamicSharedMemorySize,
                             TILE_SMEM);
        attr_done = 1;
    }

    const int NC = N_NODES * C;
    const int mtiles = (N_NODES + 127) / 128;   // 391

    // BN + weights + layer-0 GEMM1 first (GEMM lands in the ncu -s 5 window)
    zero_pre<<<(N_NODES + 255) / 256, 256>>>();
    bn_stats<<<2048, 128>>>(x);
    bn_coef<<<1, 128>>>(gamma, beta);
    bn_apply<<<(NC + 255) / 256, 256>>>(x);
    prep_weights<<<256, 256>>>(convW, w_ih, w_hh, b_hh);
    gemm_bf16<<<dim3(4, mtiles), 256, TILE_SMEM>>>(xhh, B0h, 512, bias512,
                                                   mgh, mh, N_NODES);
    // CSR build (independent of GEMM1)
    detect_kernel<<<1, 64>>>((const long long*)eidx);
    normalize_edges<<<(N_EDGES + 255) / 256, 256>>>(eidx);
    deg_kernel<<<(N_EDGES + 255) / 256, 256>>>();
    scan_part<<<SCAN_BLOCKS, 256>>>();
    scan_top<<<1, 256>>>();
    scan_block<<<SCAN_BLOCKS, 256>>>();
    invdeg_kernel<<<(N_NODES + 255) / 256, 256>>>();
    scatter_k<<<(N_EDGES + 255) / 256, 256>>>();

    // layer 0 rest
    agg_csr<<<(N_NODES + 7) / 8, 256>>>(eattr, edgeW);
    gemm_bf16<<<dim3(3, mtiles), 256, TILE_SMEM>>>(aggh, B2h, 384, b_ih,
                                                   gi, nullptr, N_NODES);
    gru_gates<<<(NC + 255) / 256, 256>>>(xh, h, hh, 0);

    // layer 1
    gemm_bf16<<<dim3(4, mtiles), 256, TILE_SMEM>>>(hh, B1h, 512, bias512,
                                                   mgh, mh, N_NODES);
    agg_csr<<<(N_NODES + 7) / 8, 256>>>(eattr, edgeW);
    gemm_bf16<<<dim3(3, mtiles), 256, TILE_SMEM>>>(aggh, B2h, 384, b_ih,
                                                   gi, nullptr, N_NODES);
    gru_gates<<<(NC + 255) / 256, 256>>>(h, out, nullptr, 1);
}

// round 5
// speedup vs baseline: 2.7726x; 1.4888x over previous
#include <cuda_runtime.h>
#include <cuda_bf16.h>
#include <math.h>
#include <stdint.h>

#define N_NODES 50000
#define N_EDGES 600000
#define C 128
#define EC 16
#define BN_EPS 1e-5f
#define ALPHA 0.5f

typedef __nv_bfloat16 bf16;
typedef __nv_bfloat162 bf162;

// ---------------- device scratch (no allocations allowed) ----------------
__device__ float g_xh[N_NODES * C];          // BN output (x0) fp32
__device__ bf16  g_xhh[N_NODES * C];         // BN output bf16 (GEMM A)
__device__ float g_h[N_NODES * C];           // h after layer 0 (fp32)
__device__ bf16  g_hh[N_NODES * C];          // h bf16 (GEMM A, layer 1)
__device__ float g_gh[N_NODES * 384];        // gh = h@w_hh^T + b_hh (fp32)
__device__ bf16  g_mh[N_NODES * C];          // bf16 copy of m (gather source)
__device__ bf16  g_aggh[N_NODES * C];        // (agg/deg) bf16 (GEMM2 A)
__device__ float g_gi[N_NODES * 384];        // gi fp32
__device__ bf16  g_eah[N_EDGES * C];         // ea per CSR position, bf16
__device__ int   g_src[N_EDGES];
__device__ int   g_dst[N_EDGES];
__device__ int   g_csr_src[N_EDGES];
__device__ int   g_csr_eid[N_EDGES];
__device__ int   g_degi[N_NODES];
__device__ int   g_ptr[N_NODES + 1];
__device__ int   g_cur[N_NODES];
__device__ int   g_bsum[256];
__device__ int   g_boff[256];
__device__ float g_invdeg[N_NODES];
__device__ float g_sum[C];
__device__ float g_sq[C];
__device__ float g_scale[C];
__device__ float g_shift[C];
__device__ bf16  g_B0h[512 * 128];           // [convW0^T | w_hh] rows n, k contig
__device__ bf16  g_B1h[512 * 128];           // [convW1^T | w_hh]
__device__ bf16  g_B2h[384 * 128];           // w_ih (already [384][128] k-contig)
__device__ bf16  g_eWh[128 * 16];            // edge_W^T: [n][k] bf16
__device__ float g_bias512[512];             // [0...0 | b_hh]
__device__ int   g_is64;

// ---------------- small PTX helpers ----------------
__device__ __forceinline__ uint32_t smem_u32(const void* p) {
    uint32_t a;
    asm("{ .reg .u64 t; cvta.to.shared.u64 t, %1; cvt.u32.u64 %0, t; }"
        : "=r"(a) : "l"(p));
    return a;
}
__device__ __forceinline__ void ldmx4(uint32_t* r, uint32_t addr) {
    asm volatile("ldmatrix.sync.aligned.m8n8.x4.shared.b16 {%0,%1,%2,%3}, [%4];"
        : "=r"(r[0]), "=r"(r[1]), "=r"(r[2]), "=r"(r[3]) : "r"(addr));
}
__device__ __forceinline__ void mma_bf16(float* d, const uint32_t* a,
                                         const uint32_t* b) {
    asm volatile(
        "mma.sync.aligned.m16n8k16.row.col.f32.bf16.bf16.f32 "
        "{%0,%1,%2,%3}, {%4,%5,%6,%7}, {%8,%9}, {%0,%1,%2,%3};"
        : "+f"(d[0]), "+f"(d[1]), "+f"(d[2]), "+f"(d[3])
        : "r"(a[0]), "r"(a[1]), "r"(a[2]), "r"(a[3]), "r"(b[0]), "r"(b[1]));
}

// ---------------- edge_index dtype detection ----------------
__global__ void detect_kernel(const long long* __restrict__ raw) {
    __shared__ int bad;
    if (threadIdx.x == 0) bad = 0;
    __syncthreads();
    long long v = raw[threadIdx.x];   // 64 threads
    if (v < 0 || v >= (1LL << 31)) atomicExch(&bad, 1);
    __syncthreads();
    if (threadIdx.x == 0) g_is64 = bad ? 0 : 1;
}

// normalize + degree count fused
__global__ void normalize_edges(const void* __restrict__ raw) {
    int e = blockIdx.x * blockDim.x + threadIdx.x;
    if (e >= N_EDGES) return;
    int s, d;
    if (g_is64) {
        const long long* p = (const long long*)raw;
        s = (int)p[e];
        d = (int)p[N_EDGES + e];
    } else {
        const int* p = (const int*)raw;
        s = p[e];
        d = p[N_EDGES + e];
    }
    g_src[e] = s;
    g_dst[e] = d;
    atomicAdd(&g_degi[d], 1);
}

// ---------------- zero / CSR build ----------------
__global__ void zero_pre() {
    int i = blockIdx.x * blockDim.x + threadIdx.x;
    if (i < N_NODES) g_degi[i] = 0;
    if (i < C) { g_sum[i] = 0.f; g_sq[i] = 0.f; }
}

__global__ void invdeg_kernel() {
    int i = blockIdx.x * blockDim.x + threadIdx.x;
    if (i < N_NODES) g_invdeg[i] = 1.0f / fmaxf((float)g_degi[i], 1.0f);
}

#define SCAN_BLOCKS 196
__global__ void scan_part() {           // 196 x 256
    __shared__ int sh[256];
    int i = blockIdx.x * 256 + threadIdx.x;
    sh[threadIdx.x] = (i < N_NODES) ? g_degi[i] : 0;
    __syncthreads();
    for (int s = 128; s > 0; s >>= 1) {
        if (threadIdx.x < s) sh[threadIdx.x] += sh[threadIdx.x + s];
        __syncthreads();
    }
    if (threadIdx.x == 0) g_bsum[blockIdx.x] = sh[0];
}

__global__ void scan_top() {            // 1 x 256
    __shared__ int sh[256];
    int t = threadIdx.x;
    int own = (t < SCAN_BLOCKS) ? g_bsum[t] : 0;
    sh[t] = own;
    __syncthreads();
    for (int s = 1; s < 256; s <<= 1) {
        int v = (t >= s) ? sh[t - s] : 0;
        __syncthreads();
        sh[t] += v;
        __syncthreads();
    }
    if (t < SCAN_BLOCKS) g_boff[t] = sh[t] - own;   // exclusive
}

__global__ void scan_block() {          // 196 x 256
    __shared__ int sh[256];
    int t = threadIdx.x;
    int i = blockIdx.x * 256 + t;
    int v = (i < N_NODES) ? g_degi[i] : 0;
    sh[t] = v;
    __syncthreads();
    for (int s = 1; s < 256; s <<= 1) {
        int u = (t >= s) ? sh[t - s] : 0;
        __syncthreads();
        sh[t] += u;
        __syncthreads();
    }
    int excl = sh[t] - v + g_boff[blockIdx.x];
    if (i < N_NODES) { g_ptr[i] = excl; g_cur[i] = excl; }
    if (i == N_NODES - 1) g_ptr[N_NODES] = excl + v;
}

__global__ void scatter_k() {
    int e = blockIdx.x * blockDim.x + threadIdx.x;
    if (e >= N_EDGES) return;
    int pos = atomicAdd(&g_cur[g_dst[e]], 1);
    g_csr_src[pos] = g_src[e];
    g_csr_eid[pos] = e;
}

// ---------------- batchnorm ----------------
__global__ void bn_stats(const float* __restrict__ x) {
    // 1024 blocks x 256 threads; 2 rows/block-slice, 4-way unrolled (MLP=4)
    int c = threadIdx.x & 127;
    int half = threadIdx.x >> 7;
    float s = 0.f, q = 0.f;
    int stride = gridDim.x * 8;
    for (int base = blockIdx.x * 8 + half * 4; base < N_NODES; base += stride) {
        float v0 = 0.f, v1 = 0.f, v2 = 0.f, v3 = 0.f;
        if (base + 0 < N_NODES) v0 = x[(size_t)(base + 0) * C + c];
        if (base + 1 < N_NODES) v1 = x[(size_t)(base + 1) * C + c];
        if (base + 2 < N_NODES) v2 = x[(size_t)(base + 2) * C + c];
        if (base + 3 < N_NODES) v3 = x[(size_t)(base + 3) * C + c];
        s += (v0 + v1) + (v2 + v3);
        q += (v0 * v0 + v1 * v1) + (v2 * v2 + v3 * v3);
    }
    atomicAdd(&g_sum[c], s);
    atomicAdd(&g_sq[c], q);
}

__global__ void bn_coef(const float* __restrict__ gamma, const float* __restrict__ beta) {
    int c = threadIdx.x;
    float mean = g_sum[c] / (float)N_NODES;
    float var = g_sq[c] / (float)N_NODES - mean * mean;
    float sc = gamma[c] * rsqrtf(var + BN_EPS);
    g_scale[c] = sc;
    g_shift[c] = beta[c] - mean * sc;
}

__global__ void bn_apply(const float* __restrict__ x) {
    int idx = blockIdx.x * blockDim.x + threadIdx.x;   // float4 index
    if (idx >= N_NODES * C / 4) return;
    int c4 = (idx & 31) * 4;
    float4 v = *(const float4*)(x + (size_t)idx * 4);
    float4 sc = *(const float4*)&g_scale[c4];
    float4 sh = *(const float4*)&g_shift[c4];
    v.x = v.x * sc.x + sh.x;
    v.y = v.y * sc.y + sh.y;
    v.z = v.z * sc.z + sh.z;
    v.w = v.w * sc.w + sh.w;
    *(float4*)&g_xh[(size_t)idx * 4] = v;
    bf162 p0 = __float22bfloat162_rn(make_float2(v.x, v.y));
    bf162 p1 = __float22bfloat162_rn(make_float2(v.z, v.w));
    uint2 st;
    st.x = *(uint32_t*)&p0;
    st.y = *(uint32_t*)&p1;
    *(uint2*)&g_xhh[(size_t)idx * 4] = st;
}

// ---------------- weight prep (bf16) ----------------
__global__ void prep_weights(const float* __restrict__ convW,
                             const float* __restrict__ w_ih,
                             const float* __restrict__ w_hh,
                             const float* __restrict__ b_hh,
                             const float* __restrict__ eW) {
    int idx = blockIdx.x * blockDim.x + threadIdx.x;
    int total = 512 * 128;
    for (int t = idx; t < total; t += gridDim.x * blockDim.x) {
        int n = t >> 7;
        int k = t & 127;
        float v0, v1;
        if (n < 128) {
            v0 = convW[k * 128 + n];
            v1 = convW[128 * 128 + k * 128 + n];
        } else {
            float w = w_hh[(n - 128) * 128 + k];
            v0 = w; v1 = w;
        }
        g_B0h[t] = __float2bfloat16(v0);
        g_B1h[t] = __float2bfloat16(v1);
        if (t < 384 * 128) g_B2h[t] = __float2bfloat16(w_ih[t]);
        if (t < 128 * 16) {
            int nn = t >> 4, kk = t & 15;
            g_eWh[t] = __float2bfloat16(eW[kk * 128 + nn]);
        }
        if (t < 512) g_bias512[t] = (t < 128) ? 0.f : b_hh[t - 128];
    }
}

// ---------------- bf16 tensor-core GEMM ----------------
// C = A[M x 128] @ Bt^T + bias; Bt [nb][128] k-contiguous, both bf16.
// CTA 128x128, 256 threads = 8 warps (2M x 4N), warp 64x32.
// gh_mode: cols<128 -> write only bf16 mcopy; cols>=128 -> fp32 Cmat[r][cc-128],
//          row stride 384. Otherwise plain fp32 Cmat stride nb.
#define SPADH 136
#define ASH_BYTES (128 * SPADH * 2)
#define TILE_SMEM (2 * ASH_BYTES)

__global__ __launch_bounds__(256, 2)
void gemm_bf16(const bf16* __restrict__ A, const bf16* __restrict__ Bt, int nb,
               const float* __restrict__ bias, float* __restrict__ Cmat,
               bf16* __restrict__ mcopy, int gh_mode, int M) {
    extern __shared__ bf16 smh[];
    bf16* As = smh;                     // [128][SPADH]
    bf16* Bs = smh + 128 * SPADH;

    int tid = threadIdx.x, wid = tid >> 5, lane = tid & 31;
    int rowBase = blockIdx.y * 128, colBase = blockIdx.x * 128;
    uint32_t As_u = smem_u32(As), Bs_u = smem_u32(Bs);

#pragma unroll
    for (int i = 0; i < 8; i++) {
        int c = tid + i * 256;
        int r = c >> 4, o = c & 15;
        int grow = rowBase + r;
        uint32_t sa = As_u + r * (SPADH * 2) + o * 16;
        int gr = (grow < M) ? grow : (M - 1);
        const void* ga = A + (size_t)gr * 128 + o * 8;
        uint32_t sz = (grow < M) ? 16u : 0u;
        asm volatile("cp.async.cg.shared.global [%0], [%1], 16, %2;"
                     :: "r"(sa), "l"(ga), "r"(sz));
    }
#pragma unroll
    for (int i = 0; i < 8; i++) {
        int c = tid + i * 256;
        int r = c >> 4, o = c & 15;
        uint32_t sa = Bs_u + r * (SPADH * 2) + o * 16;
        const void* ga = Bt + (size_t)(colBase + r) * 128 + o * 8;
        asm volatile("cp.async.cg.shared.global [%0], [%1], 16;"
                     :: "r"(sa), "l"(ga));
    }
    asm volatile("cp.async.commit_group;");
    asm volatile("cp.async.wait_group 0;" ::: "memory");
    __syncthreads();

    int mBase = (wid >> 2) * 64, nBase = (wid & 3) * 32;
    int mat = lane >> 3, rin = lane & 7;

    uint32_t aAddr[4];
#pragma unroll
    for (int mi = 0; mi < 4; mi++) {
        int row = mBase + mi * 16 + (mat & 1) * 8 + rin;
        int koff = (mat >> 1) * 8;
        aAddr[mi] = As_u + row * (SPADH * 2) + koff * 2;
    }
    uint32_t bAddr[2];
#pragma unroll
    for (int j = 0; j < 2; j++) {
        int row = nBase + j * 16 + (mat >> 1) * 8 + rin;
        int koff = (mat & 1) * 8;
        bAddr[j] = Bs_u + row * (SPADH * 2) + koff * 2;
    }

    float acc[4][4][4] = {};
#pragma unroll
    for (int ks = 0; ks < 8; ks++) {
        uint32_t afr[4][4], bfr[2][4];
#pragma unroll
        for (int mi = 0; mi < 4; mi++) ldmx4(afr[mi], aAddr[mi] + ks * 32);
#pragma unroll
        for (int j = 0; j < 2; j++) ldmx4(bfr[j], bAddr[j] + ks * 32);
#pragma unroll
        for (int mi = 0; mi < 4; mi++) {
            mma_bf16(acc[mi][0], afr[mi], &bfr[0][0]);
            mma_bf16(acc[mi][1], afr[mi], &bfr[0][2]);
            mma_bf16(acc[mi][2], afr[mi], &bfr[1][0]);
            mma_bf16(acc[mi][3], afr[mi], &bfr[1][2]);
        }
    }

    int qr = lane >> 2, qc = lane & 3;
#pragma unroll
    for (int mi = 0; mi < 4; mi++) {
        int r0 = rowBase + mBase + mi * 16 + qr;
#pragma unroll
        for (int ni = 0; ni < 4; ni++) {
            int cc = colBase + nBase + ni * 8 + qc * 2;
            float2 bv = *(const float2*)(bias + cc);
            float2 o0 = make_float2(acc[mi][ni][0] + bv.x, acc[mi][ni][1] + bv.y);
            float2 o1 = make_float2(acc[mi][ni][2] + bv.x, acc[mi][ni][3] + bv.y);
            if (gh_mode) {
                if (cc < 128) {
                    if (r0 < M)
                        *(bf162*)(mcopy + (size_t)r0 * 128 + cc) =
                            __float22bfloat162_rn(o0);
                    if (r0 + 8 < M)
                        *(bf162*)(mcopy + (size_t)(r0 + 8) * 128 + cc) =
                            __float22bfloat162_rn(o1);
                } else {
                    if (r0 < M)
                        *(float2*)(Cmat + (size_t)r0 * 384 + (cc - 128)) = o0;
                    if (r0 + 8 < M)
                        *(float2*)(Cmat + (size_t)(r0 + 8) * 384 + (cc - 128)) = o1;
                }
            } else {
                if (r0 < M) *(float2*)(Cmat + (size_t)r0 * nb + cc) = o0;
                if (r0 + 8 < M) *(float2*)(Cmat + (size_t)(r0 + 8) * nb + cc) = o1;
            }
        }
    }
}

// ---------------- ea GEMM: [600k x 16] @ [16 x 128] -> bf16, CSR order ----------
// A row p = eattr[g_csr_eid[p]]; B = edge_W^T (g_eWh [128][16]).
#define SPADE 24   // halfs per row (48B): LDSM conflict-free
__global__ __launch_bounds__(256, 4)
void ea_gemm(const float* __restrict__ eattr) {
    __shared__ bf16 As[128 * SPADE];
    __shared__ bf16 Bs[128 * SPADE];

    int tid = threadIdx.x, wid = tid >> 5, lane = tid & 31;
    int rowBase = blockIdx.x * 128;
    uint32_t As_u = smem_u32(As), Bs_u = smem_u32(Bs);

    // A: 128 rows x 16 (gather by csr_eid), each thread: 1 row-half (8 floats)
    {
        int r = tid >> 1, part = tid & 1;
        int p = rowBase + r;
        int eid = g_csr_eid[(p < N_EDGES) ? p : (N_EDGES - 1)];
        const float4* src = (const float4*)(eattr + (size_t)eid * 16 + part * 8);
        float4 v0 = src[0], v1 = src[1];
        bf162 h0 = __float22bfloat162_rn(make_float2(v0.x, v0.y));
        bf162 h1 = __float22bfloat162_rn(make_float2(v0.z, v0.w));
        bf162 h2 = __float22bfloat162_rn(make_float2(v1.x, v1.y));
        bf162 h3 = __float22bfloat162_rn(make_float2(v1.z, v1.w));
        uint4 st;
        st.x = *(uint32_t*)&h0; st.y = *(uint32_t*)&h1;
        st.z = *(uint32_t*)&h2; st.w = *(uint32_t*)&h3;
        *(uint4*)&As[r * SPADE + part * 8] = st;
    }
    // B: 128 rows(n) x 16(k) from g_eWh (bf16) — same layout
    {
        int r = tid >> 1, part = tid & 1;
        uint4 v = *(const uint4*)&g_eWh[r * 16 + part * 8];
        *(uint4*)&Bs[r * SPADE + part * 8] = v;
    }
    __syncthreads();

    int mBase = (wid >> 2) * 64, nBase = (wid & 3) * 32;
    int mat = lane >> 3, rin = lane & 7;

    uint32_t afr[4][4], bfr[2][4];
#pragma unroll
    for (int mi = 0; mi < 4; mi++) {
        int row = mBase + mi * 16 + (mat & 1) * 8 + rin;
        int koff = (mat >> 1) * 8;
        ldmx4(afr[mi], As_u + row * (SPADE * 2) + koff * 2);
    }
#pragma unroll
    for (int j = 0; j < 2; j++) {
        int row = nBase + j * 16 + (mat >> 1) * 8 + rin;
        int koff = (mat & 1) * 8;
        ldmx4(bfr[j], Bs_u + row * (SPADE * 2) + koff * 2);
    }

    float acc[4][4][4] = {};
#pragma unroll
    for (int mi = 0; mi < 4; mi++) {
        mma_bf16(acc[mi][0], afr[mi], &bfr[0][0]);
        mma_bf16(acc[mi][1], afr[mi], &bfr[0][2]);
        mma_bf16(acc[mi][2], afr[mi], &bfr[1][0]);
        mma_bf16(acc[mi][3], afr[mi], &bfr[1][2]);
    }

    int qr = lane >> 2, qc = lane & 3;
#pragma unroll
    for (int mi = 0; mi < 4; mi++) {
        int r0 = rowBase + mBase + mi * 16 + qr;
#pragma unroll
        for (int ni = 0; ni < 4; ni++) {
            int cc = nBase + ni * 8 + qc * 2;
            if (r0 < N_EDGES)
                *(bf162*)(g_eah + (size_t)r0 * 128 + cc) =
                    __float22bfloat162_rn(make_float2(acc[mi][ni][0],
                                                      acc[mi][ni][1]));
            if (r0 + 8 < N_EDGES)
                *(bf162*)(g_eah + (size_t)(r0 + 8) * 128 + cc) =
                    __float22bfloat162_rn(make_float2(acc[mi][ni][2],
                                                      acc[mi][ni][3]));
        }
    }
}

// ---------------- CSR aggregation: one warp per node ----------------
// agg[v] = invdeg[v] * sum_e relu(m_bf16[src_e] + ea_bf16[e])
__global__ void agg_csr() {
    int warp = (blockIdx.x * blockDim.x + threadIdx.x) >> 5;
    int lane = threadIdx.x & 31;
    if (warp >= N_NODES) return;

    int beg = g_ptr[warp], end = g_ptr[warp + 1];
    float4 acc = make_float4(0.f, 0.f, 0.f, 0.f);

    for (int e = beg; e < end; e++) {
        int s = g_csr_src[e];
        uint2 ev = *(const uint2*)&g_eah[(size_t)e * C + lane * 4];
        uint2 mv = *(const uint2*)&g_mh[(size_t)s * C + lane * 4];
        float2 e01 = __bfloat1622float2(*(bf162*)&ev.x);
        float2 e23 = __bfloat1622float2(*(bf162*)&ev.y);
        float2 m01 = __bfloat1622float2(*(bf162*)&mv.x);
        float2 m23 = __bfloat1622float2(*(bf162*)&mv.y);
        acc.x += fmaxf(m01.x + e01.x, 0.f);
        acc.y += fmaxf(m01.y + e01.y, 0.f);
        acc.z += fmaxf(m23.x + e23.x, 0.f);
        acc.w += fmaxf(m23.y + e23.y, 0.f);
    }
    float sc = g_invdeg[warp];
    bf162 p0 = __float22bfloat162_rn(make_float2(acc.x * sc, acc.y * sc));
    bf162 p1 = __float22bfloat162_rn(make_float2(acc.z * sc, acc.w * sc));
    uint2 st;
    st.x = *(uint32_t*)&p0;
    st.y = *(uint32_t*)&p1;
    *(uint2*)&g_aggh[(size_t)warp * C + lane * 4] = st;
}

// ---------------- GRU gates (+ optional final residual) ----------------
__global__ void gru_gates(const float* __restrict__ hin,
                          float* __restrict__ hout, bf16* __restrict__ houth,
                          int last) {
    int idx = blockIdx.x * blockDim.x + threadIdx.x;
    if (idx >= N_NODES * C) return;
    int n = idx >> 7;
    int c = idx & (C - 1);
    size_t gib = (size_t)n * 384;
    float ir = g_gi[gib + c];
    float iz = g_gi[gib + 128 + c];
    float in_ = g_gi[gib + 256 + c];
    float hr = g_gh[gib + c];
    float hz = g_gh[gib + 128 + c];
    float hn = g_gh[gib + 256 + c];
    float r = 1.f / (1.f + expf(-(ir + hr)));
    float z = 1.f / (1.f + expf(-(iz + hz)));
    float nn = tanhf(in_ + r * hn);
    float h = hin[idx];
    float hnew = (1.f - z) * nn + z * h;
    if (last) {
        hout[idx] = (1.f - ALPHA) * fmaxf(hnew, 0.f) + ALPHA * g_xh[idx];
    } else {
        hout[idx] = hnew;
        houth[idx] = __float2bfloat16(hnew);
    }
}

// ---------------- host ----------------
extern "C" void kernel_launch(void* const* d_in, const int* in_sizes, int n_in,
                              void* d_out, int out_size) {
    const float* x     = (const float*)d_in[0];
    const void*  eidx  = d_in[1];
    const float* eattr = (const float*)d_in[2];
    const float* gamma = (const float*)d_in[3];
    const float* beta  = (const float*)d_in[4];
    const float* edgeW = (const float*)d_in[5];
    const float* convW = (const float*)d_in[6];
    const float* w_ih  = (const float*)d_in[7];
    const float* w_hh  = (const float*)d_in[8];
    const float* b_ih  = (const float*)d_in[9];
    const float* b_hh  = (const float*)d_in[10];
    float* out = (float*)d_out;
    (void)in_sizes; (void)n_in; (void)out_size;

    float *xh, *h, *gh, *gi, *bias512;
    bf16 *xhh, *hh, *mh, *aggh, *B0h, *B1h, *B2h;
    void* p;
    cudaGetSymbolAddress(&p, g_xh);      xh = (float*)p;
    cudaGetSymbolAddress(&p, g_xhh);     xhh = (bf16*)p;
    cudaGetSymbolAddress(&p, g_h);       h = (float*)p;
    cudaGetSymbolAddress(&p, g_hh);      hh = (bf16*)p;
    cudaGetSymbolAddress(&p, g_gh);      gh = (float*)p;
    cudaGetSymbolAddress(&p, g_mh);      mh = (bf16*)p;
    cudaGetSymbolAddress(&p, g_aggh);    aggh = (bf16*)p;
    cudaGetSymbolAddress(&p, g_gi);      gi = (float*)p;
    cudaGetSymbolAddress(&p, g_B0h);     B0h = (bf16*)p;
    cudaGetSymbolAddress(&p, g_B1h);     B1h = (bf16*)p;
    cudaGetSymbolAddress(&p, g_B2h);     B2h = (bf16*)p;
    cudaGetSymbolAddress(&p, g_bias512); bias512 = (float*)p;

    static int attr_done = 0;
    if (!attr_done) {
        cudaFuncSetAttribute(gemm_bf16, cudaFuncAttributeMaxDynamicSharedMemorySize,
                             TILE_SMEM);
        attr_done = 1;
    }

    const int NC = N_NODES * C;
    const int mtiles = (N_NODES + 127) / 128;      // 391
    const int etiles = (N_EDGES + 127) / 128;      // 4688

    detect_kernel<<<1, 64>>>((const long long*)eidx);
    zero_pre<<<(N_NODES + 255) / 256, 256>>>();
    normalize_edges<<<(N_EDGES + 255) / 256, 256>>>(eidx);
    bn_stats<<<1024, 256>>>(x);
    bn_coef<<<1, 128>>>(gamma, beta);
    bn_apply<<<(NC / 4 + 255) / 256, 256>>>(x);
    prep_weights<<<256, 256>>>(convW, w_ih, w_hh, b_hh, edgeW);
    scan_part<<<SCAN_BLOCKS, 256>>>();
    scan_top<<<1, 256>>>();
    scan_block<<<SCAN_BLOCKS, 256>>>();
    invdeg_kernel<<<(N_NODES + 255) / 256, 256>>>();
    scatter_k<<<(N_EDGES + 255) / 256, 256>>>();
    ea_gemm<<<etiles, 256>>>(eattr);

    // layer 0
    gemm_bf16<<<dim3(4, mtiles), 256, TILE_SMEM>>>(xhh, B0h, 512, bias512,
                                                   gh, mh, 1, N_NODES);
    agg_csr<<<(N_NODES + 7) / 8, 256>>>();
    gemm_bf16<<<dim3(3, mtiles), 256, TILE_SMEM>>>(aggh, B2h, 384, b_ih,
                                                   gi, nullptr, 0, N_NODES);
    gru_gates<<<(NC + 255) / 256, 256>>>(xh, h, hh, 0);

    // layer 1
    gemm_bf16<<<dim3(4, mtiles), 256, TILE_SMEM>>>(hh, B1h, 512, bias512,
                                                   gh, mh, 1, N_NODES);
    agg_csr<<<(N_NODES + 7) / 8, 256>>>();
    gemm_bf16<<<dim3(3, mtiles), 256, TILE_SMEM>>>(aggh, B2h, 384, b_ih,
                                                   gi, nullptr, 0, N_NODES);
    gru_gates<<<(NC + 255) / 256, 256>>>(h, out, nullptr, 1);
}